// round 4
// baseline (speedup 1.0000x reference)
#include <cuda_runtime.h>

#define NN 50000
#define NE 800000
#define DIN 7
#define DD 64
#define GG 64

// ---------------- scratch (device globals; no allocation allowed) -------------
__device__ float g_xemb[NN * DD];
__device__ float g_xaggemb[NN * DD];
__device__ float g_xagg[NN * DD];
__device__ float g_ne[NN * 8];
__device__ float g_indeg[NN];
__device__ float g_degmax[GG];
__device__ float g_gagg[GG * DD];
__device__ float g_gcnt[GG];
__device__ float g_gout[GG * DD];
__device__ int   g_col[NE];
__device__ int   g_row[NE];
__device__ int   g_batch[NN];
__device__ int   g_flag[2];   // 1 => input is int64, 0 => int32

// ---------------- dtype detection -------------------------------------------
// Sample 32 odd int32 words spread across the first `n32_elems` 32-bit words
// (element count is valid for both dtypes). If the array is int64 with small
// nonneg values, all odd words (high halves) are 0. If int32, values are graph
// indices, virtually never all zero at the sampled (spread) positions.
__global__ void k_detect(const int* __restrict__ p, int n32, int slot) {
    int t = threadIdx.x;                 // 32 threads
    long long half = (long long)(n32 - 1) / 2;
    long long k = (half > 32) ? ((long long)t * (half - 1)) / 31 : (long long)t;
    long long idx = 2 * k + 1;
    int v = (idx < n32) ? p[idx] : 0;
    unsigned m = __ballot_sync(0xffffffffu, v == 0);
    if (t == 0) g_flag[slot] = (m == 0xffffffffu) ? 1 : 0;
}

__global__ void k_conv_edges(const void* __restrict__ p) {
    int e = blockIdx.x * blockDim.x + threadIdx.x;
    if (e >= NE) return;
    if (g_flag[0]) {
        const long long* q = (const long long*)p;
        g_col[e] = (int)q[e];
        g_row[e] = (int)q[NE + e];
    } else {
        const int* q = (const int*)p;
        g_col[e] = q[e];
        g_row[e] = q[NE + e];
    }
}

__global__ void k_conv_batch(const void* __restrict__ p) {
    int n = blockIdx.x * blockDim.x + threadIdx.x;
    if (n >= NN) return;
    if (g_flag[1]) {
        const long long* q = (const long long*)p;
        g_batch[n] = (int)q[n];
    } else {
        g_batch[n] = ((const int*)p)[n];
    }
}

// ---------------- zero kernels ------------------------------------------------
__global__ void k_zero_small() {
    int i = blockIdx.x * blockDim.x + threadIdx.x;
    if (i < NN * 8) g_ne[i] = 0.f;
    if (i < NN)     g_indeg[i] = 0.f;
    if (i < GG)     { g_degmax[i] = 0.f; g_gcnt[i] = 0.f; }
    if (i < GG * DD) g_gagg[i] = 0.f;
}

__global__ void k_zero_xagg() {
    int i = blockIdx.x * blockDim.x + threadIdx.x;
    if (i < NN * DD) g_xagg[i] = 0.f;
}

// ---------------- node embedding: x_emb = relu(x @ W_en + b_en) --------------
__global__ void k_nodeemb(const float* __restrict__ x,
                          const float* __restrict__ W,
                          const float* __restrict__ b) {
    int idx = blockIdx.x * blockDim.x + threadIdx.x;
    if (idx >= NN * DD) return;
    int n = idx >> 6, o = idx & 63;
    const float* xr = x + n * DIN;
    float acc = b[o];
#pragma unroll
    for (int i = 0; i < DIN; i++) acc = fmaf(xr[i], W[i * DD + o], acc);
    g_xemb[idx] = fmaxf(acc, 0.f);
}

// ---------------- edge scatter #1: ne += [x[col], edge_attr], indeg count ----
__global__ void k_edge1(const float* __restrict__ x, const float* __restrict__ ea) {
    int idx = blockIdx.x * blockDim.x + threadIdx.x;
    int e = idx >> 3, j = idx & 7;
    if (e >= NE) return;
    int r = g_row[e];
    float v;
    if (j < 7) v = x[g_col[e] * DIN + j];
    else       v = ea[e];
    atomicAdd(&g_ne[r * 8 + j], v);
    if (j == 7) atomicAdd(&g_indeg[r], 1.f);
}

// ---------------- per-graph degree max ---------------------------------------
__global__ void k_degmax(const float* __restrict__ degree) {
    int n = blockIdx.x * blockDim.x + threadIdx.x;
    if (n >= NN) return;
    atomicMax((unsigned int*)&g_degmax[g_batch[n]], __float_as_uint(degree[n]));
}

// ---------------- x_agg_emb ----------------------------------------------------
// node_edge = relu((ne/cnt) @ W_ene + b_ene)  [63]
// x_agg_emb = relu([node_edge, deg_norm] @ W_agg + b_agg)  [64]
__global__ void k_node2(const float* __restrict__ Wene, const float* __restrict__ bene,
                        const float* __restrict__ Wagg, const float* __restrict__ bagg) {
    __shared__ float sh[4][DD];
    int gl = threadIdx.x >> 6, o = threadIdx.x & 63;
    int n = blockIdx.x * 4 + gl;
    bool act = (n < NN);
    float t = 0.f;
    if (act) {
        if (o < 63) {
            float rc = 1.f / fmaxf(g_indeg[n], 1.f);
            float acc = bene[o];
#pragma unroll
            for (int j = 0; j < 8; j++)
                acc = fmaf(g_ne[n * 8 + j] * rc, Wene[j * 63 + o], acc);
            t = fmaxf(acc, 0.f);
        } else {
            t = g_degmax[g_batch[n]];
        }
    }
    sh[gl][o] = t;
    __syncthreads();
    if (act) {
        float acc = bagg[o];
#pragma unroll 16
        for (int k = 0; k < DD; k++) acc = fmaf(sh[gl][k], Wagg[k * DD + o], acc);
        g_xaggemb[n * DD + o] = fmaxf(acc, 0.f);
    }
}

// ---------------- per-layer edge scatter: xagg += ea * x_emb[col] -------------
__global__ void k_edgeL(const float* __restrict__ ea) {
    int idx = blockIdx.x * blockDim.x + threadIdx.x;   // up to 51.2M < 2^31
    int e = idx >> 6, j = idx & 63;
    if (e >= NE) return;
    float w = ea[e];
    atomicAdd(&g_xagg[g_row[e] * DD + j], w * g_xemb[g_col[e] * DD + j]);
}

// ---------------- per-layer node update ---------------------------------------
// m      = relu([xagg/cnt, x_agg_emb] @ Wm + bm)
// x_emb  = relu([x_emb, m] @ Wu + bu)
__global__ void k_nodeL(const float* __restrict__ Wm, const float* __restrict__ bm,
                        const float* __restrict__ Wu, const float* __restrict__ bu) {
    __shared__ float sh[4][2 * DD];
    int gl = threadIdx.x >> 6, o = threadIdx.x & 63;
    int n = blockIdx.x * 4 + gl;
    bool act = (n < NN);
    float xe = 0.f;
    if (act) {
        float rc = 1.f / fmaxf(g_indeg[n], 1.f);
        sh[gl][o]      = g_xagg[n * DD + o] * rc;
        sh[gl][DD + o] = g_xaggemb[n * DD + o];
        xe = g_xemb[n * DD + o];
    }
    __syncthreads();
    float m = 0.f;
    if (act) {
        float acc = bm[o];
#pragma unroll 16
        for (int j = 0; j < 2 * DD; j++) acc = fmaf(sh[gl][j], Wm[j * DD + o], acc);
        m = fmaxf(acc, 0.f);
    }
    __syncthreads();
    if (act) { sh[gl][o] = xe; sh[gl][DD + o] = m; }
    __syncthreads();
    if (act) {
        float acc = bu[o];
#pragma unroll 16
        for (int j = 0; j < 2 * DD; j++) acc = fmaf(sh[gl][j], Wu[j * DD + o], acc);
        g_xemb[n * DD + o] = fmaxf(acc, 0.f);
    }
}

// ---------------- graph pooling -----------------------------------------------
__global__ void k_gscatter() {
    int idx = blockIdx.x * blockDim.x + threadIdx.x;
    if (idx >= NN * DD) return;
    int n = idx >> 6, j = idx & 63;
    atomicAdd(&g_gagg[g_batch[n] * DD + j], g_xemb[idx]);
}

__global__ void k_gcnt() {
    int n = blockIdx.x * blockDim.x + threadIdx.x;
    if (n >= NN) return;
    atomicAdd(&g_gcnt[g_batch[n]], 1.f);
}

__global__ void k_ggemm(const float* __restrict__ Wg, const float* __restrict__ bg) {
    int idx = blockIdx.x * blockDim.x + threadIdx.x;
    if (idx >= GG * DD) return;
    int g = idx >> 6, o = idx & 63;
    float rc = 1.f / fmaxf(g_gcnt[g], 1.f);
    float acc = bg[o];
#pragma unroll 16
    for (int k = 0; k < DD; k++)
        acc = fmaf(g_gagg[g * DD + k] * rc, Wg[k * DD + o], acc);
    g_gout[idx] = acc;   // no relu here (reference applies relu to the concat input)
}

// ---------------- readout: q = relu([gout[batch], x_emb]) @ W_r + b_r ---------
__global__ void k_final(const float* __restrict__ Wr, const float* __restrict__ br,
                        float* __restrict__ out) {
    int gidx = blockIdx.x * blockDim.x + threadIdx.x;
    int n = gidx >> 5;
    int lane = threadIdx.x & 31;
    if (n >= NN) return;
    int b = g_batch[n];
    float acc = fmaxf(g_gout[b * DD + lane], 0.f)       * Wr[lane]
              + fmaxf(g_gout[b * DD + 32 + lane], 0.f)  * Wr[32 + lane]
              + g_xemb[n * DD + lane]                    * Wr[DD + lane]       // x_emb >= 0 already
              + g_xemb[n * DD + 32 + lane]               * Wr[DD + 32 + lane];
#pragma unroll
    for (int s = 16; s > 0; s >>= 1) acc += __shfl_down_sync(0xffffffffu, acc, s);
    if (lane == 0) out[n] = acc + br[0];
}

// ---------------- launch -------------------------------------------------------
extern "C" void kernel_launch(void* const* d_in, const int* in_sizes, int n_in,
                              void* d_out, int out_size) {
    const float* x      = (const float*)d_in[0];
    const void*  eidx   = d_in[1];
    const float* ea     = (const float*)d_in[2];
    const void*  batch  = d_in[3];
    const float* degree = (const float*)d_in[4];
    // d_in[5] = num_graphs (scalar) if present; weights follow.
    int wb = (n_in >= 20) ? 6 : 5;
    const float* W_en  = (const float*)d_in[wb + 0];
    const float* b_en  = (const float*)d_in[wb + 1];
    const float* W_ene = (const float*)d_in[wb + 2];
    const float* b_ene = (const float*)d_in[wb + 3];
    const float* W_agg = (const float*)d_in[wb + 4];
    const float* b_agg = (const float*)d_in[wb + 5];
    const float* Wm    = (const float*)d_in[wb + 6];
    const float* bm    = (const float*)d_in[wb + 7];
    const float* Wu    = (const float*)d_in[wb + 8];
    const float* bu    = (const float*)d_in[wb + 9];
    const float* W_g   = (const float*)d_in[wb + 10];
    const float* b_g   = (const float*)d_in[wb + 11];
    const float* W_r   = (const float*)d_in[wb + 12];
    const float* b_r   = (const float*)d_in[wb + 13];
    float* out = (float*)d_out;

    k_detect<<<1, 32>>>((const int*)eidx, 2 * NE, 0);
    k_detect<<<1, 32>>>((const int*)batch, NN, 1);
    k_conv_edges<<<(NE + 255) / 256, 256>>>(eidx);
    k_conv_batch<<<(NN + 255) / 256, 256>>>(batch);
    k_zero_small<<<(NN * 8 + 255) / 256, 256>>>();

    k_nodeemb<<<(NN * DD + 255) / 256, 256>>>(x, W_en, b_en);
    k_edge1<<<(NE * 8 + 255) / 256, 256>>>(x, ea);
    k_degmax<<<(NN + 255) / 256, 256>>>(degree);
    k_node2<<<(NN + 3) / 4, 256>>>(W_ene, b_ene, W_agg, b_agg);

    for (int l = 0; l < 3; l++) {
        k_zero_xagg<<<(NN * DD + 255) / 256, 256>>>();
        k_edgeL<<<(NE * DD + 255) / 256, 256>>>(ea);
        k_nodeL<<<(NN + 3) / 4, 256>>>(Wm + l * 2 * DD * DD, bm + l * DD,
                                       Wu + l * 2 * DD * DD, bu + l * DD);
    }

    k_gscatter<<<(NN * DD + 255) / 256, 256>>>();
    k_gcnt<<<(NN + 255) / 256, 256>>>();
    k_ggemm<<<(GG * DD + 255) / 256, 256>>>(W_g, b_g);
    k_final<<<(NN * 32 + 255) / 256, 256>>>(W_r, b_r, out);
}

// round 5
// speedup vs baseline: 1.3141x; 1.3141x over previous
#include <cuda_runtime.h>

#define NN 50000
#define NE 800000
#define DIN 7
#define DD 64
#define GG 64

// ---------------- scratch (device globals; no allocation allowed) -------------
__device__ float g_xemb[NN * DD];
__device__ float g_xaggemb[NN * DD];
__device__ float g_xagg[NN * DD];
__device__ float g_ne[NN * 8];
__device__ float g_indeg[NN];
__device__ float g_degmax[GG];
__device__ float g_gagg[GG * DD];
__device__ float g_gcnt[GG];
__device__ float g_gout[GG * DD];
__device__ int   g_col[NE];
__device__ int   g_row[NE];
__device__ int   g_batch[NN];
__device__ int   g_flag[2];   // 1 => input is int64, 0 => int32

// ---------------- vector reduction helper (sm_90+) ----------------------------
__device__ __forceinline__ void red4(float* p, float4 v) {
    asm volatile("red.global.add.v4.f32 [%0], {%1,%2,%3,%4};"
                 :: "l"(p), "f"(v.x), "f"(v.y), "f"(v.z), "f"(v.w)
                 : "memory");
}

// ---------------- dtype detection ---------------------------------------------
__global__ void k_detect(const int* __restrict__ p, int n32, int slot) {
    int t = threadIdx.x;                 // 32 threads
    long long half = (long long)(n32 - 1) / 2;
    long long k = (half > 32) ? ((long long)t * (half - 1)) / 31 : (long long)t;
    long long idx = 2 * k + 1;
    int v = (idx < n32) ? p[idx] : 0;
    unsigned m = __ballot_sync(0xffffffffu, v == 0);
    if (t == 0) g_flag[slot] = (m == 0xffffffffu) ? 1 : 0;
}

__global__ void k_conv_edges(const void* __restrict__ p) {
    int e = blockIdx.x * blockDim.x + threadIdx.x;
    if (e >= NE) return;
    if (g_flag[0]) {
        const long long* q = (const long long*)p;
        g_col[e] = (int)q[e];
        g_row[e] = (int)q[NE + e];
    } else {
        const int* q = (const int*)p;
        g_col[e] = q[e];
        g_row[e] = q[NE + e];
    }
}

// batch conversion + per-graph degree max + per-graph node count (fused)
__global__ void k_conv_batch(const void* __restrict__ p, const float* __restrict__ degree) {
    int n = blockIdx.x * blockDim.x + threadIdx.x;
    if (n >= NN) return;
    int b;
    if (g_flag[1]) b = (int)((const long long*)p)[n];
    else           b = ((const int*)p)[n];
    g_batch[n] = b;
    atomicMax((unsigned int*)&g_degmax[b], __float_as_uint(degree[n]));
    atomicAdd(&g_gcnt[b], 1.f);
}

// ---------------- single zero kernel (float4 stores) ---------------------------
__global__ void k_zero() {
    int i = blockIdx.x * blockDim.x + threadIdx.x;
    float4 z = make_float4(0.f, 0.f, 0.f, 0.f);
    if (i < NN * 16)  ((float4*)g_xagg)[i] = z;     // 50000*64 floats
    if (i < NN * 2)   ((float4*)g_ne)[i] = z;       // 50000*8 floats
    if (i < NN / 4)   ((float4*)g_indeg)[i] = z;    // 50000 floats (divisible by 4)
    if (i < GG * 16)  ((float4*)g_gagg)[i] = z;     // 64*64 floats
    if (i < GG / 4) { ((float4*)g_degmax)[i] = z; ((float4*)g_gcnt)[i] = z; }
}

// ---------------- node embedding: x_emb = relu(x @ W_en + b_en) ---------------
__global__ void k_nodeemb(const float* __restrict__ x,
                          const float* __restrict__ W,
                          const float* __restrict__ b) {
    __shared__ float sx[4][DIN];
    int gl = threadIdx.x >> 6, o = threadIdx.x & 63;
    int n = blockIdx.x * 4 + gl;
    if (o < DIN && n < NN) sx[gl][o] = x[n * DIN + o];
    __syncthreads();
    if (n >= NN) return;
    float acc = b[o];
#pragma unroll
    for (int i = 0; i < DIN; i++) acc = fmaf(sx[gl][i], W[i * DD + o], acc);
    g_xemb[n * DD + o] = fmaxf(acc, 0.f);
}

// ---------------- edge scatter #1: ne += [x[col], edge_attr], indeg count -----
// 2 threads per edge, each issues one v4 reduction.
__global__ void k_edge1(const float* __restrict__ x, const float* __restrict__ ea) {
    int idx = blockIdx.x * blockDim.x + threadIdx.x;
    int e = idx >> 1, s = idx & 1;
    if (e >= NE) return;
    int c = g_col[e], r = g_row[e];
    const float* xr = x + c * DIN;
    float4 v;
    if (s == 0) {
        v.x = xr[0]; v.y = xr[1]; v.z = xr[2]; v.w = xr[3];
    } else {
        v.x = xr[4]; v.y = xr[5]; v.z = xr[6]; v.w = ea[e];
        atomicAdd(&g_indeg[r], 1.f);
    }
    red4(g_ne + r * 8 + s * 4, v);
}

// ---------------- x_agg_emb -----------------------------------------------------
__global__ void k_node2(const float* __restrict__ Wene, const float* __restrict__ bene,
                        const float* __restrict__ Wagg, const float* __restrict__ bagg) {
    __shared__ float sh[4][DD];
    int gl = threadIdx.x >> 6, o = threadIdx.x & 63;
    int n = blockIdx.x * 4 + gl;
    bool act = (n < NN);
    float t = 0.f;
    if (act) {
        if (o < 63) {
            float rc = 1.f / fmaxf(g_indeg[n], 1.f);
            float acc = bene[o];
#pragma unroll
            for (int j = 0; j < 8; j++)
                acc = fmaf(g_ne[n * 8 + j] * rc, Wene[j * 63 + o], acc);
            t = fmaxf(acc, 0.f);
        } else {
            t = g_degmax[g_batch[n]];
        }
    }
    sh[gl][o] = t;
    __syncthreads();
    if (act) {
        float acc = bagg[o];
#pragma unroll 16
        for (int k = 0; k < DD; k++) acc = fmaf(sh[gl][k], Wagg[k * DD + o], acc);
        g_xaggemb[n * DD + o] = fmaxf(acc, 0.f);
    }
}

// ---------------- per-layer edge scatter: xagg += ea * x_emb[col] --------------
// 8 threads per edge; each handles 8 floats via two float4 gathers + two v4 reds.
__global__ void k_edgeL(const float* __restrict__ ea) {
    int idx = blockIdx.x * blockDim.x + threadIdx.x;   // NE*8 = 6.4M
    int e = idx >> 3, q = idx & 7;
    if (e >= NE) return;
    float w = ea[e];
    int c = g_col[e], r = g_row[e];
    const float4* src = (const float4*)(g_xemb + c * DD);
    float4 a = src[2 * q], b = src[2 * q + 1];
    a.x *= w; a.y *= w; a.z *= w; a.w *= w;
    b.x *= w; b.y *= w; b.z *= w; b.w *= w;
    float* dst = g_xagg + r * DD + 8 * q;
    red4(dst, a);
    red4(dst + 4, b);
}

// ---------------- per-layer node update (also re-zeroes xagg for next layer) ---
__global__ void k_nodeL(const float* __restrict__ Wm, const float* __restrict__ bm,
                        const float* __restrict__ Wu, const float* __restrict__ bu) {
    __shared__ float sh[4][2 * DD];
    int gl = threadIdx.x >> 6, o = threadIdx.x & 63;
    int n = blockIdx.x * 4 + gl;
    bool act = (n < NN);
    float xe = 0.f;
    if (act) {
        float rc = 1.f / fmaxf(g_indeg[n], 1.f);
        float xa = g_xagg[n * DD + o];
        g_xagg[n * DD + o] = 0.f;          // pre-zero for the next layer's scatter
        sh[gl][o]      = xa * rc;
        sh[gl][DD + o] = g_xaggemb[n * DD + o];
        xe = g_xemb[n * DD + o];
    }
    __syncthreads();
    float m = 0.f;
    if (act) {
        float acc = bm[o];
#pragma unroll 16
        for (int j = 0; j < 2 * DD; j++) acc = fmaf(sh[gl][j], Wm[j * DD + o], acc);
        m = fmaxf(acc, 0.f);
    }
    __syncthreads();
    if (act) { sh[gl][o] = xe; sh[gl][DD + o] = m; }
    __syncthreads();
    if (act) {
        float acc = bu[o];
#pragma unroll 16
        for (int j = 0; j < 2 * DD; j++) acc = fmaf(sh[gl][j], Wu[j * DD + o], acc);
        g_xemb[n * DD + o] = fmaxf(acc, 0.f);
    }
}

// ---------------- graph pooling: sorted-batch local accumulation ---------------
// Thread handles one 4-column chunk for 16 consecutive nodes; since batch is
// sorted, runs are long -> ~1 v4 red per thread instead of 16.
__global__ void k_gscatter() {
    int idx = blockIdx.x * blockDim.x + threadIdx.x;   // NN/16 * 16 = 50000
    int c  = idx & 15;
    int n0 = (idx >> 4) * 16;
    if (n0 >= NN) return;
    float4 acc = make_float4(0.f, 0.f, 0.f, 0.f);
    int curb = g_batch[n0];
#pragma unroll
    for (int k = 0; k < 16; k++) {
        int n = n0 + k;
        int b = g_batch[n];
        if (b != curb) {
            red4(g_gagg + curb * DD + c * 4, acc);
            acc = make_float4(0.f, 0.f, 0.f, 0.f);
            curb = b;
        }
        float4 v = ((const float4*)g_xemb)[n * 16 + c];
        acc.x += v.x; acc.y += v.y; acc.z += v.z; acc.w += v.w;
    }
    red4(g_gagg + curb * DD + c * 4, acc);
}

__global__ void k_ggemm(const float* __restrict__ Wg, const float* __restrict__ bg) {
    int idx = blockIdx.x * blockDim.x + threadIdx.x;
    if (idx >= GG * DD) return;
    int g = idx >> 6, o = idx & 63;
    float rc = 1.f / fmaxf(g_gcnt[g], 1.f);
    float acc = bg[o];
#pragma unroll 16
    for (int k = 0; k < DD; k++)
        acc = fmaf(g_gagg[g * DD + k] * rc, Wg[k * DD + o], acc);
    g_gout[idx] = acc;   // no relu here (reference applies relu to the concat input)
}

// ---------------- readout: q = relu([gout[batch], x_emb]) @ W_r + b_r ----------
__global__ void k_final(const float* __restrict__ Wr, const float* __restrict__ br,
                        float* __restrict__ out) {
    int gidx = blockIdx.x * blockDim.x + threadIdx.x;
    int n = gidx >> 5;
    int lane = threadIdx.x & 31;
    if (n >= NN) return;
    int b = g_batch[n];
    float acc = fmaxf(g_gout[b * DD + lane], 0.f)       * Wr[lane]
              + fmaxf(g_gout[b * DD + 32 + lane], 0.f)  * Wr[32 + lane]
              + g_xemb[n * DD + lane]                    * Wr[DD + lane]      // x_emb >= 0 already
              + g_xemb[n * DD + 32 + lane]               * Wr[DD + 32 + lane];
#pragma unroll
    for (int s = 16; s > 0; s >>= 1) acc += __shfl_down_sync(0xffffffffu, acc, s);
    if (lane == 0) out[n] = acc + br[0];
}

// ---------------- launch --------------------------------------------------------
extern "C" void kernel_launch(void* const* d_in, const int* in_sizes, int n_in,
                              void* d_out, int out_size) {
    const float* x      = (const float*)d_in[0];
    const void*  eidx   = d_in[1];
    const float* ea     = (const float*)d_in[2];
    const void*  batch  = d_in[3];
    const float* degree = (const float*)d_in[4];
    int wb = (n_in >= 20) ? 6 : 5;
    const float* W_en  = (const float*)d_in[wb + 0];
    const float* b_en  = (const float*)d_in[wb + 1];
    const float* W_ene = (const float*)d_in[wb + 2];
    const float* b_ene = (const float*)d_in[wb + 3];
    const float* W_agg = (const float*)d_in[wb + 4];
    const float* b_agg = (const float*)d_in[wb + 5];
    const float* Wm    = (const float*)d_in[wb + 6];
    const float* bm    = (const float*)d_in[wb + 7];
    const float* Wu    = (const float*)d_in[wb + 8];
    const float* bu    = (const float*)d_in[wb + 9];
    const float* W_g   = (const float*)d_in[wb + 10];
    const float* b_g   = (const float*)d_in[wb + 11];
    const float* W_r   = (const float*)d_in[wb + 12];
    const float* b_r   = (const float*)d_in[wb + 13];
    float* out = (float*)d_out;

    k_detect<<<1, 32>>>((const int*)eidx, 2 * NE, 0);
    k_detect<<<1, 32>>>((const int*)batch, NN, 1);
    k_zero<<<(NN * 16 + 255) / 256, 256>>>();
    k_conv_edges<<<(NE + 255) / 256, 256>>>(eidx);
    k_conv_batch<<<(NN + 255) / 256, 256>>>(batch, degree);

    k_nodeemb<<<(NN + 3) / 4, 256>>>(x, W_en, b_en);
    k_edge1<<<(NE * 2 + 255) / 256, 256>>>(x, ea);
    k_node2<<<(NN + 3) / 4, 256>>>(W_ene, b_ene, W_agg, b_agg);

    for (int l = 0; l < 3; l++) {
        k_edgeL<<<(NE * 8 + 255) / 256, 256>>>(ea);
        k_nodeL<<<(NN + 3) / 4, 256>>>(Wm + l * 2 * DD * DD, bm + l * DD,
                                       Wu + l * 2 * DD * DD, bu + l * DD);
    }

    k_gscatter<<<(NN + 255) / 256, 256>>>();
    k_ggemm<<<(GG * DD + 255) / 256, 256>>>(W_g, b_g);
    k_final<<<(NN * 32 + 255) / 256, 256>>>(W_r, b_r, out);
}

// round 7
// speedup vs baseline: 1.5276x; 1.1625x over previous
#include <cuda_runtime.h>

#define NN 50000
#define NE 800000
#define DIN 7
#define DD 64
#define GG 64
#define NB_SCAN 196   // ceil(NN/256)

// ---------------- scratch (device globals; no allocation allowed) -------------
__device__ float g_xembA[NN * DD];
__device__ float g_xembB[NN * DD];
__device__ float g_xaggemb[NN * DD];
__device__ float g_degmax[GG];
__device__ float g_gagg[GG * DD];
__device__ float g_gcnt[GG];
__device__ float g_gout[GG * DD];
__device__ int   g_col[NE];
__device__ int   g_row[NE];
__device__ int2  g_cw[NE];          // sorted-by-row packed {col, w_bits}
__device__ int   g_rowptr[NN + 1];
__device__ int   g_cnt[NN];         // histogram
__device__ int   g_cnt2[NN];        // scatter cursors
__device__ int   g_bsum[NB_SCAN];
__device__ int   g_boff[NB_SCAN];
__device__ int   g_batch[NN];
__device__ int   g_flag[2];         // 1 => input is int64, 0 => int32

// ---------------- vector reduction helper (sm_90+) ----------------------------
__device__ __forceinline__ void red4(float* p, float4 v) {
    asm volatile("red.global.add.v4.f32 [%0], {%1,%2,%3,%4};"
                 :: "l"(p), "f"(v.x), "f"(v.y), "f"(v.z), "f"(v.w)
                 : "memory");
}

// ---------------- dtype detection ---------------------------------------------
__global__ void k_detect(const int* __restrict__ p, int n32, int slot) {
    int t = threadIdx.x;                 // 32 threads
    long long half = (long long)(n32 - 1) / 2;
    long long k = (half > 32) ? ((long long)t * (half - 1)) / 31 : (long long)t;
    long long idx = 2 * k + 1;
    int v = (idx < n32) ? p[idx] : 0;
    unsigned m = __ballot_sync(0xffffffffu, v == 0);
    if (t == 0) g_flag[slot] = (m == 0xffffffffu) ? 1 : 0;
}

// ---------------- zero (ints + pooling buffers) --------------------------------
__global__ void k_zero() {
    int i = blockIdx.x * blockDim.x + threadIdx.x;
    int4 zi = make_int4(0, 0, 0, 0);
    float4 zf = make_float4(0.f, 0.f, 0.f, 0.f);
    if (i < NN / 4) { ((int4*)g_cnt)[i] = zi; ((int4*)g_cnt2)[i] = zi; }
    if (i < GG * 16) ((float4*)g_gagg)[i] = zf;
    if (i < GG / 4) { ((float4*)g_degmax)[i] = zf; ((float4*)g_gcnt)[i] = zf; }
}

// edge conversion + row histogram
__global__ void k_conv_edges(const void* __restrict__ p) {
    int e = blockIdx.x * blockDim.x + threadIdx.x;
    if (e >= NE) return;
    int c, r;
    if (g_flag[0]) {
        const long long* q = (const long long*)p;
        c = (int)q[e]; r = (int)q[NE + e];
    } else {
        const int* q = (const int*)p;
        c = q[e]; r = q[NE + e];
    }
    g_col[e] = c;
    g_row[e] = r;
    atomicAdd(&g_cnt[r], 1);
}

// batch conversion + per-graph degree max + per-graph node count (fused)
__global__ void k_conv_batch(const void* __restrict__ p, const float* __restrict__ degree) {
    int n = blockIdx.x * blockDim.x + threadIdx.x;
    if (n >= NN) return;
    int b;
    if (g_flag[1]) b = (int)((const long long*)p)[n];
    else           b = ((const int*)p)[n];
    g_batch[n] = b;
    atomicMax((unsigned int*)&g_degmax[b], __float_as_uint(degree[n]));
    atomicAdd(&g_gcnt[b], 1.f);
}

// ---------------- 3-kernel exclusive scan of g_cnt -> g_rowptr -----------------
__global__ void k_scanA() {                         // 196 blocks x 256
    __shared__ int sh[256];
    int i = blockIdx.x * 256 + threadIdx.x;
    sh[threadIdx.x] = (i < NN) ? g_cnt[i] : 0;
    __syncthreads();
    for (int s = 128; s > 0; s >>= 1) {
        if (threadIdx.x < s) sh[threadIdx.x] += sh[threadIdx.x + s];
        __syncthreads();
    }
    if (threadIdx.x == 0) g_bsum[blockIdx.x] = sh[0];
}

__global__ void k_scanB() {                         // 1 block x 256
    __shared__ int sh[256];
    int t = threadIdx.x;
    int v = (t < NB_SCAN) ? g_bsum[t] : 0;
    sh[t] = v;
    __syncthreads();
    for (int s = 1; s < 256; s <<= 1) {
        int add = (t >= s) ? sh[t - s] : 0;
        __syncthreads();
        sh[t] += add;
        __syncthreads();
    }
    if (t < NB_SCAN) g_boff[t] = sh[t] - v;         // exclusive
    if (t == 0) g_rowptr[NN] = NE;
}

__global__ void k_scanC() {                         // 196 blocks x 256
    __shared__ int sh[256];
    int t = threadIdx.x;
    int i = blockIdx.x * 256 + t;
    int v = (i < NN) ? g_cnt[i] : 0;
    sh[t] = v;
    __syncthreads();
    for (int s = 1; s < 256; s <<= 1) {
        int add = (t >= s) ? sh[t - s] : 0;
        __syncthreads();
        sh[t] += add;
        __syncthreads();
    }
    if (i < NN) g_rowptr[i] = g_boff[blockIdx.x] + sh[t] - v;
}

// scatter edges into CSR order, packing {col, w}
__global__ void k_scatter(const float* __restrict__ ea) {
    int e = blockIdx.x * blockDim.x + threadIdx.x;
    if (e >= NE) return;
    int r = g_row[e];
    int pos = g_rowptr[r] + atomicAdd(&g_cnt2[r], 1);
    g_cw[pos] = make_int2(g_col[e], __float_as_int(ea[e]));
}

// ---------------- node embedding: x_emb = relu(x @ W_en + b_en) ---------------
__global__ void k_nodeemb(const float* __restrict__ x,
                          const float* __restrict__ W,
                          const float* __restrict__ b) {
    __shared__ float sx[4][DIN];
    int gl = threadIdx.x >> 6, o = threadIdx.x & 63;
    int n = blockIdx.x * 4 + gl;
    if (o < DIN && n < NN) sx[gl][o] = x[n * DIN + o];
    __syncthreads();
    if (n >= NN) return;
    float acc = b[o];
#pragma unroll
    for (int i = 0; i < DIN; i++) acc = fmaf(sx[gl][i], W[i * DD + o], acc);
    g_xembA[n * DD + o] = fmaxf(acc, 0.f);
}

// ---------------- fused: CSR gather of [x[col], ea] + node_edge + x_agg_emb ----
// Per node: 64 threads = 8 groups x 8 features. Group g strides the edge list.
__global__ void k_node2(const float* __restrict__ x,
                        const float* __restrict__ Wene, const float* __restrict__ bene,
                        const float* __restrict__ Wagg, const float* __restrict__ bagg) {
    __shared__ float part[4][8][9];   // [node][group][feature] (padded)
    __shared__ float ne[4][8];
    __shared__ float sh[4][DD];
    int gl = threadIdx.x >> 6, t = threadIdx.x & 63;
    int n = blockIdx.x * 4 + gl;
    bool act = (n < NN);
    int grp = t >> 3, f = t & 7;
    int p0 = 0, deg = 0;
    if (act) { p0 = g_rowptr[n]; deg = g_rowptr[n + 1] - p0; }
    float acc = 0.f;
    for (int k = grp; k < deg; k += 8) {
        int2 cw = g_cw[p0 + k];
        float v = (f < 7) ? x[cw.x * DIN + f] : __int_as_float(cw.y);
        acc += v;
    }
    part[gl][grp][f] = acc;
    __syncthreads();
    if (t < 8) {
        float s = 0.f;
#pragma unroll
        for (int g2 = 0; g2 < 8; g2++) s += part[gl][g2][t];
        ne[gl][t] = s;
    }
    __syncthreads();
    float tt = 0.f;
    if (act) {
        if (t < 63) {
            float rc = 1.f / fmaxf((float)deg, 1.f);
            float a = bene[t];
#pragma unroll
            for (int j = 0; j < 8; j++)
                a = fmaf(ne[gl][j] * rc, Wene[j * 63 + t], a);
            tt = fmaxf(a, 0.f);
        } else {
            tt = g_degmax[g_batch[n]];
        }
    }
    sh[gl][t] = tt;
    __syncthreads();
    if (act) {
        float a = bagg[t];
#pragma unroll 16
        for (int k = 0; k < DD; k++) a = fmaf(sh[gl][k], Wagg[k * DD + t], a);
        g_xaggemb[n * DD + t] = fmaxf(a, 0.f);
    }
}

// ---------------- fused per-layer: CSR gather + both node GEMMs ---------------
// flip=0: src=A dst=B ; flip=1: src=B dst=A
__global__ void k_layer(const float* __restrict__ Wm, const float* __restrict__ bm,
                        const float* __restrict__ Wu, const float* __restrict__ bu,
                        int flip) {
    const float* __restrict__ src = flip ? g_xembB : g_xembA;
    float*       __restrict__ dst = flip ? g_xembA : g_xembB;
    __shared__ float sh[4][2 * DD];
    int gl = threadIdx.x >> 6, o = threadIdx.x & 63;
    int n = blockIdx.x * 4 + gl;
    bool act = (n < NN);
    int p0 = 0, deg = 0;
    if (act) { p0 = g_rowptr[n]; deg = g_rowptr[n + 1] - p0; }
    float accg = 0.f;
    int k = 0;
    for (; k + 4 <= deg; k += 4) {               // modest unroll: 4 loads in flight
        int2 c0 = g_cw[p0 + k],     c1 = g_cw[p0 + k + 1];
        int2 c2 = g_cw[p0 + k + 2], c3 = g_cw[p0 + k + 3];
        float v0 = src[c0.x * DD + o], v1 = src[c1.x * DD + o];
        float v2 = src[c2.x * DD + o], v3 = src[c3.x * DD + o];
        accg = fmaf(__int_as_float(c0.y), v0, accg);
        accg = fmaf(__int_as_float(c1.y), v1, accg);
        accg = fmaf(__int_as_float(c2.y), v2, accg);
        accg = fmaf(__int_as_float(c3.y), v3, accg);
    }
    for (; k < deg; k++) {
        int2 cw = g_cw[p0 + k];
        accg = fmaf(__int_as_float(cw.y), src[cw.x * DD + o], accg);
    }
    float xe = 0.f;
    if (act) {
        float rc = 1.f / fmaxf((float)deg, 1.f);
        sh[gl][o]      = accg * rc;
        sh[gl][DD + o] = g_xaggemb[n * DD + o];
        xe = src[n * DD + o];
    }
    __syncthreads();
    float m = 0.f;
    if (act) {
        float a = bm[o];
#pragma unroll 16
        for (int j = 0; j < 2 * DD; j++) a = fmaf(sh[gl][j], Wm[j * DD + o], a);
        m = fmaxf(a, 0.f);
    }
    __syncthreads();
    if (act) { sh[gl][o] = xe; sh[gl][DD + o] = m; }
    __syncthreads();
    if (act) {
        float a = bu[o];
#pragma unroll 16
        for (int j = 0; j < 2 * DD; j++) a = fmaf(sh[gl][j], Wu[j * DD + o], a);
        dst[n * DD + o] = fmaxf(a, 0.f);
    }
}

// ---------------- graph pooling: sorted-batch local accumulation --------------
__global__ void k_gscatter() {
    int idx = blockIdx.x * blockDim.x + threadIdx.x;   // 50000 threads
    int c  = idx & 15;
    int n0 = (idx >> 4) * 16;
    if (n0 >= NN) return;
    float4 acc = make_float4(0.f, 0.f, 0.f, 0.f);
    int curb = g_batch[n0];
#pragma unroll
    for (int k = 0; k < 16; k++) {
        int n = n0 + k;
        int b = g_batch[n];
        if (b != curb) {
            red4(g_gagg + curb * DD + c * 4, acc);
            acc = make_float4(0.f, 0.f, 0.f, 0.f);
            curb = b;
        }
        float4 v = ((const float4*)g_xembB)[n * 16 + c];
        acc.x += v.x; acc.y += v.y; acc.z += v.z; acc.w += v.w;
    }
    red4(g_gagg + curb * DD + c * 4, acc);
}

__global__ void k_ggemm(const float* __restrict__ Wg, const float* __restrict__ bg) {
    int idx = blockIdx.x * blockDim.x + threadIdx.x;
    if (idx >= GG * DD) return;
    int g = idx >> 6, o = idx & 63;
    float rc = 1.f / fmaxf(g_gcnt[g], 1.f);
    float acc = bg[o];
#pragma unroll 16
    for (int k = 0; k < DD; k++)
        acc = fmaf(g_gagg[g * DD + k] * rc, Wg[k * DD + o], acc);
    g_gout[idx] = acc;   // no relu (reference applies relu to the concat input)
}

// ---------------- readout: q = relu([gout[batch], x_emb]) @ W_r + b_r ----------
__global__ void k_final(const float* __restrict__ Wr, const float* __restrict__ br,
                        float* __restrict__ out) {
    int gidx = blockIdx.x * blockDim.x + threadIdx.x;
    int n = gidx >> 5;
    int lane = threadIdx.x & 31;
    if (n >= NN) return;
    int b = g_batch[n];
    float acc = fmaxf(g_gout[b * DD + lane], 0.f)       * Wr[lane]
              + fmaxf(g_gout[b * DD + 32 + lane], 0.f)  * Wr[32 + lane]
              + g_xembB[n * DD + lane]                   * Wr[DD + lane]      // x_emb >= 0
              + g_xembB[n * DD + 32 + lane]              * Wr[DD + 32 + lane];
#pragma unroll
    for (int s = 16; s > 0; s >>= 1) acc += __shfl_down_sync(0xffffffffu, acc, s);
    if (lane == 0) out[n] = acc + br[0];
}

// ---------------- launch --------------------------------------------------------
extern "C" void kernel_launch(void* const* d_in, const int* in_sizes, int n_in,
                              void* d_out, int out_size) {
    const float* x      = (const float*)d_in[0];
    const void*  eidx   = d_in[1];
    const float* ea     = (const float*)d_in[2];
    const void*  batch  = d_in[3];
    const float* degree = (const float*)d_in[4];
    int wb = (n_in >= 20) ? 6 : 5;
    const float* W_en  = (const float*)d_in[wb + 0];
    const float* b_en  = (const float*)d_in[wb + 1];
    const float* W_ene = (const float*)d_in[wb + 2];
    const float* b_ene = (const float*)d_in[wb + 3];
    const float* W_agg = (const float*)d_in[wb + 4];
    const float* b_agg = (const float*)d_in[wb + 5];
    const float* Wm    = (const float*)d_in[wb + 6];
    const float* bm    = (const float*)d_in[wb + 7];
    const float* Wu    = (const float*)d_in[wb + 8];
    const float* bu    = (const float*)d_in[wb + 9];
    const float* W_g   = (const float*)d_in[wb + 10];
    const float* b_g   = (const float*)d_in[wb + 11];
    const float* W_r   = (const float*)d_in[wb + 12];
    const float* b_r   = (const float*)d_in[wb + 13];
    float* out = (float*)d_out;

    k_detect<<<1, 32>>>((const int*)eidx, 2 * NE, 0);
    k_detect<<<1, 32>>>((const int*)batch, NN, 1);
    k_zero<<<(GG * 16 + NN / 4 + 255) / 256, 256>>>();
    k_conv_edges<<<(NE + 255) / 256, 256>>>(eidx);
    k_conv_batch<<<(NN + 255) / 256, 256>>>(batch, degree);

    // CSR build
    k_scanA<<<NB_SCAN, 256>>>();
    k_scanB<<<1, 256>>>();
    k_scanC<<<NB_SCAN, 256>>>();
    k_scatter<<<(NE + 255) / 256, 256>>>(ea);

    k_nodeemb<<<(NN + 3) / 4, 256>>>(x, W_en, b_en);
    k_node2<<<(NN + 3) / 4, 256>>>(x, W_ene, b_ene, W_agg, b_agg);

    for (int l = 0; l < 3; l++) {
        k_layer<<<(NN + 3) / 4, 256>>>(Wm + l * 2 * DD * DD, bm + l * DD,
                                       Wu + l * 2 * DD * DD, bu + l * DD, l & 1);
    }

    k_gscatter<<<(NN + 255) / 256, 256>>>();
    k_ggemm<<<(GG * DD + 255) / 256, 256>>>(W_g, b_g);
    k_final<<<(NN * 32 + 255) / 256, 256>>>(W_r, b_r, out);
}

// round 8
// speedup vs baseline: 1.9867x; 1.3005x over previous
#include <cuda_runtime.h>

#define NN 50000
#define NE 800000
#define DIN 7
#define DD 64
#define GG 64
#define NB_SCAN 196   // ceil(NN/256)
#define NT 32         // nodes per k_layer block
#define PAD 36        // padded row stride for act[][] (16B aligned, conflict-lite)

// ---------------- scratch (device globals; no allocation allowed) -------------
__device__ float g_xembA[NN * DD];
__device__ float g_xembB[NN * DD];
__device__ float g_xaggemb[NN * DD];
__device__ float g_degmax[GG];
__device__ float g_gagg[GG * DD];
__device__ float g_gcnt[GG];
__device__ float g_gout[GG * DD];
__device__ int   g_col[NE];
__device__ int   g_row[NE];
__device__ int2  g_cw[NE];          // sorted-by-row packed {col, w_bits}
__device__ int   g_rowptr[NN + 1];
__device__ int   g_cnt[NN];         // histogram
__device__ int   g_cnt2[NN];        // scatter cursors
__device__ int   g_bsum[NB_SCAN];
__device__ int   g_boff[NB_SCAN];
__device__ int   g_batch[NN];
__device__ int   g_flag[2];         // 1 => input is int64, 0 => int32

// ---------------- vector reduction helper (sm_90+) ----------------------------
__device__ __forceinline__ void red4(float* p, float4 v) {
    asm volatile("red.global.add.v4.f32 [%0], {%1,%2,%3,%4};"
                 :: "l"(p), "f"(v.x), "f"(v.y), "f"(v.z), "f"(v.w)
                 : "memory");
}

// ---------------- dtype detection ---------------------------------------------
__global__ void k_detect(const int* __restrict__ p, int n32, int slot) {
    int t = threadIdx.x;                 // 32 threads
    long long half = (long long)(n32 - 1) / 2;
    long long k = (half > 32) ? ((long long)t * (half - 1)) / 31 : (long long)t;
    long long idx = 2 * k + 1;
    int v = (idx < n32) ? p[idx] : 0;
    unsigned m = __ballot_sync(0xffffffffu, v == 0);
    if (t == 0) g_flag[slot] = (m == 0xffffffffu) ? 1 : 0;
}

// ---------------- zero (ints + pooling buffers) --------------------------------
__global__ void k_zero() {
    int i = blockIdx.x * blockDim.x + threadIdx.x;
    int4 zi = make_int4(0, 0, 0, 0);
    float4 zf = make_float4(0.f, 0.f, 0.f, 0.f);
    if (i < NN / 4) { ((int4*)g_cnt)[i] = zi; ((int4*)g_cnt2)[i] = zi; }
    if (i < GG * 16) ((float4*)g_gagg)[i] = zf;
    if (i < GG / 4) { ((float4*)g_degmax)[i] = zf; ((float4*)g_gcnt)[i] = zf; }
}

// edge conversion + row histogram
__global__ void k_conv_edges(const void* __restrict__ p) {
    int e = blockIdx.x * blockDim.x + threadIdx.x;
    if (e >= NE) return;
    int c, r;
    if (g_flag[0]) {
        const long long* q = (const long long*)p;
        c = (int)q[e]; r = (int)q[NE + e];
    } else {
        const int* q = (const int*)p;
        c = q[e]; r = q[NE + e];
    }
    g_col[e] = c;
    g_row[e] = r;
    atomicAdd(&g_cnt[r], 1);
}

// batch conversion + per-graph degree max + per-graph node count (fused)
__global__ void k_conv_batch(const void* __restrict__ p, const float* __restrict__ degree) {
    int n = blockIdx.x * blockDim.x + threadIdx.x;
    if (n >= NN) return;
    int b;
    if (g_flag[1]) b = (int)((const long long*)p)[n];
    else           b = ((const int*)p)[n];
    g_batch[n] = b;
    atomicMax((unsigned int*)&g_degmax[b], __float_as_uint(degree[n]));
    atomicAdd(&g_gcnt[b], 1.f);
}

// ---------------- 3-kernel exclusive scan of g_cnt -> g_rowptr -----------------
__global__ void k_scanA() {                         // 196 blocks x 256
    __shared__ int sh[256];
    int i = blockIdx.x * 256 + threadIdx.x;
    sh[threadIdx.x] = (i < NN) ? g_cnt[i] : 0;
    __syncthreads();
    for (int s = 128; s > 0; s >>= 1) {
        if (threadIdx.x < s) sh[threadIdx.x] += sh[threadIdx.x + s];
        __syncthreads();
    }
    if (threadIdx.x == 0) g_bsum[blockIdx.x] = sh[0];
}

__global__ void k_scanB() {                         // 1 block x 256
    __shared__ int sh[256];
    int t = threadIdx.x;
    int v = (t < NB_SCAN) ? g_bsum[t] : 0;
    sh[t] = v;
    __syncthreads();
    for (int s = 1; s < 256; s <<= 1) {
        int add = (t >= s) ? sh[t - s] : 0;
        __syncthreads();
        sh[t] += add;
        __syncthreads();
    }
    if (t < NB_SCAN) g_boff[t] = sh[t] - v;         // exclusive
    if (t == 0) g_rowptr[NN] = NE;
}

__global__ void k_scanC() {                         // 196 blocks x 256
    __shared__ int sh[256];
    int t = threadIdx.x;
    int i = blockIdx.x * 256 + t;
    int v = (i < NN) ? g_cnt[i] : 0;
    sh[t] = v;
    __syncthreads();
    for (int s = 1; s < 256; s <<= 1) {
        int add = (t >= s) ? sh[t - s] : 0;
        __syncthreads();
        sh[t] += add;
        __syncthreads();
    }
    if (i < NN) g_rowptr[i] = g_boff[blockIdx.x] + sh[t] - v;
}

// scatter edges into CSR order, packing {col, w}
__global__ void k_scatter(const float* __restrict__ ea) {
    int e = blockIdx.x * blockDim.x + threadIdx.x;
    if (e >= NE) return;
    int r = g_row[e];
    int pos = g_rowptr[r] + atomicAdd(&g_cnt2[r], 1);
    g_cw[pos] = make_int2(g_col[e], __float_as_int(ea[e]));
}

// ---------------- node embedding: x_emb = relu(x @ W_en + b_en) ---------------
__global__ void k_nodeemb(const float* __restrict__ x,
                          const float* __restrict__ W,
                          const float* __restrict__ b) {
    __shared__ float sx[4][DIN];
    int gl = threadIdx.x >> 6, o = threadIdx.x & 63;
    int n = blockIdx.x * 4 + gl;
    if (o < DIN && n < NN) sx[gl][o] = x[n * DIN + o];
    __syncthreads();
    if (n >= NN) return;
    float acc = b[o];
#pragma unroll
    for (int i = 0; i < DIN; i++) acc = fmaf(sx[gl][i], W[i * DD + o], acc);
    g_xembA[n * DD + o] = fmaxf(acc, 0.f);
}

// ---------------- fused: CSR gather of [x[col], ea] + node_edge + x_agg_emb ----
__global__ void k_node2(const float* __restrict__ x,
                        const float* __restrict__ Wene, const float* __restrict__ bene,
                        const float* __restrict__ Wagg, const float* __restrict__ bagg) {
    __shared__ float part[4][8][9];   // [node][group][feature] (padded)
    __shared__ float ne[4][8];
    __shared__ float sh[4][DD];
    int gl = threadIdx.x >> 6, t = threadIdx.x & 63;
    int n = blockIdx.x * 4 + gl;
    bool act = (n < NN);
    int grp = t >> 3, f = t & 7;
    int p0 = 0, deg = 0;
    if (act) { p0 = g_rowptr[n]; deg = g_rowptr[n + 1] - p0; }
    float acc = 0.f;
    for (int k = grp; k < deg; k += 8) {
        int2 cw = g_cw[p0 + k];
        float v = (f < 7) ? x[cw.x * DIN + f] : __int_as_float(cw.y);
        acc += v;
    }
    part[gl][grp][f] = acc;
    __syncthreads();
    if (t < 8) {
        float s = 0.f;
#pragma unroll
        for (int g2 = 0; g2 < 8; g2++) s += part[gl][g2][t];
        ne[gl][t] = s;
    }
    __syncthreads();
    float tt = 0.f;
    if (act) {
        if (t < 63) {
            float rc = 1.f / fmaxf((float)deg, 1.f);
            float a = bene[t];
#pragma unroll
            for (int j = 0; j < 8; j++)
                a = fmaf(ne[gl][j] * rc, Wene[j * 63 + t], a);
            tt = fmaxf(a, 0.f);
        } else {
            tt = g_degmax[g_batch[n]];
        }
    }
    sh[gl][t] = tt;
    __syncthreads();
    if (act) {
        float a = bagg[t];
#pragma unroll 16
        for (int k = 0; k < DD; k++) a = fmaf(sh[gl][k], Wagg[k * DD + t], a);
        g_xaggemb[n * DD + t] = fmaxf(a, 0.f);
    }
}

// ---------------- fused per-layer: CSR gather + register-blocked node GEMMs ----
// Block = 256 threads, NT=32 nodes.
//  Gather: 8 reps x 4 nodes; warp-per-node (coalesced), results transposed into
//          act1[j][node] (j = feature). act2[0..63][node] = x_emb (for GEMM2).
//  GEMM:   thread (o = t&63, ng = t>>6) computes column o for 8 nodes
//          ng*8..ng*8+7. Per j: 1 weight LDG + 2 broadcast LDS.128 + 8 FFMA.
//          Weights read once per 32 nodes (8x less traffic than per-4).
__global__ void __launch_bounds__(256) k_layer(
        const float* __restrict__ Wm, const float* __restrict__ bm,
        const float* __restrict__ Wu, const float* __restrict__ bu,
        int flip) {
    const float* __restrict__ src = flip ? g_xembB : g_xembA;
    float*       __restrict__ dst = flip ? g_xembA : g_xembB;
    __shared__ float act1[2 * DD][PAD];   // GEMM1 input: [xagg*rc ; xaggemb]
    __shared__ float act2[2 * DD][PAD];   // GEMM2 input: [x_emb ; m]
    int t = threadIdx.x;
    int gl = t >> 6;          // 0..3
    int o  = t & 63;          // output/feature column
    int n0 = blockIdx.x * NT;

    // ---- gather phase: warp-per-node, 8 reps ----
#pragma unroll 1
    for (int rep = 0; rep < 8; rep++) {
        int ln = rep * 4 + gl;
        int n = n0 + ln;
        float accg = 0.f, xe = 0.f, xae = 0.f;
        int deg = 0;
        if (n < NN) {
            int p0 = g_rowptr[n];
            deg = g_rowptr[n + 1] - p0;
            int k = 0;
            for (; k + 4 <= deg; k += 4) {
                int2 c0 = g_cw[p0 + k],     c1 = g_cw[p0 + k + 1];
                int2 c2 = g_cw[p0 + k + 2], c3 = g_cw[p0 + k + 3];
                float v0 = src[c0.x * DD + o], v1 = src[c1.x * DD + o];
                float v2 = src[c2.x * DD + o], v3 = src[c3.x * DD + o];
                accg = fmaf(__int_as_float(c0.y), v0, accg);
                accg = fmaf(__int_as_float(c1.y), v1, accg);
                accg = fmaf(__int_as_float(c2.y), v2, accg);
                accg = fmaf(__int_as_float(c3.y), v3, accg);
            }
            for (; k < deg; k++) {
                int2 cw = g_cw[p0 + k];
                accg = fmaf(__int_as_float(cw.y), src[cw.x * DD + o], accg);
            }
            xe  = src[n * DD + o];
            xae = g_xaggemb[n * DD + o];
        }
        float rc = 1.f / fmaxf((float)deg, 1.f);
        act1[o][ln]      = accg * rc;
        act1[DD + o][ln] = xae;
        act2[o][ln]      = xe;
    }
    __syncthreads();

    // ---- GEMM1: m = relu([xagg, xaggemb] @ Wm + bm) ----
    float m[8];
    {
        float b0 = bm[o];
#pragma unroll
        for (int i = 0; i < 8; i++) m[i] = b0;
#pragma unroll 4
        for (int j = 0; j < 2 * DD; j++) {
            float w = Wm[j * DD + o];
            float4 a0 = *(const float4*)&act1[j][gl * 8];
            float4 a1 = *(const float4*)&act1[j][gl * 8 + 4];
            m[0] = fmaf(w, a0.x, m[0]); m[1] = fmaf(w, a0.y, m[1]);
            m[2] = fmaf(w, a0.z, m[2]); m[3] = fmaf(w, a0.w, m[3]);
            m[4] = fmaf(w, a1.x, m[4]); m[5] = fmaf(w, a1.y, m[5]);
            m[6] = fmaf(w, a1.z, m[6]); m[7] = fmaf(w, a1.w, m[7]);
        }
#pragma unroll
        for (int i = 0; i < 8; i++)
            act2[DD + o][gl * 8 + i] = fmaxf(m[i], 0.f);
    }
    __syncthreads();

    // ---- GEMM2: x_emb' = relu([x_emb, m] @ Wu + bu) ----
    {
        float b0 = bu[o];
#pragma unroll
        for (int i = 0; i < 8; i++) m[i] = b0;
#pragma unroll 4
        for (int j = 0; j < 2 * DD; j++) {
            float w = Wu[j * DD + o];
            float4 a0 = *(const float4*)&act2[j][gl * 8];
            float4 a1 = *(const float4*)&act2[j][gl * 8 + 4];
            m[0] = fmaf(w, a0.x, m[0]); m[1] = fmaf(w, a0.y, m[1]);
            m[2] = fmaf(w, a0.z, m[2]); m[3] = fmaf(w, a0.w, m[3]);
            m[4] = fmaf(w, a1.x, m[4]); m[5] = fmaf(w, a1.y, m[5]);
            m[6] = fmaf(w, a1.z, m[6]); m[7] = fmaf(w, a1.w, m[7]);
        }
#pragma unroll
        for (int i = 0; i < 8; i++) {
            int n = n0 + gl * 8 + i;
            if (n < NN) dst[n * DD + o] = fmaxf(m[i], 0.f);
        }
    }
}

// ---------------- graph pooling: sorted-batch local accumulation --------------
__global__ void k_gscatter() {
    int idx = blockIdx.x * blockDim.x + threadIdx.x;   // 50000 threads
    int c  = idx & 15;
    int n0 = (idx >> 4) * 16;
    if (n0 >= NN) return;
    float4 acc = make_float4(0.f, 0.f, 0.f, 0.f);
    int curb = g_batch[n0];
#pragma unroll
    for (int k = 0; k < 16; k++) {
        int n = n0 + k;
        int b = g_batch[n];
        if (b != curb) {
            red4(g_gagg + curb * DD + c * 4, acc);
            acc = make_float4(0.f, 0.f, 0.f, 0.f);
            curb = b;
        }
        float4 v = ((const float4*)g_xembB)[n * 16 + c];
        acc.x += v.x; acc.y += v.y; acc.z += v.z; acc.w += v.w;
    }
    red4(g_gagg + curb * DD + c * 4, acc);
}

__global__ void k_ggemm(const float* __restrict__ Wg, const float* __restrict__ bg) {
    int idx = blockIdx.x * blockDim.x + threadIdx.x;
    if (idx >= GG * DD) return;
    int g = idx >> 6, o = idx & 63;
    float rc = 1.f / fmaxf(g_gcnt[g], 1.f);
    float acc = bg[o];
#pragma unroll 16
    for (int k = 0; k < DD; k++)
        acc = fmaf(g_gagg[g * DD + k] * rc, Wg[k * DD + o], acc);
    g_gout[idx] = acc;   // no relu (reference applies relu to the concat input)
}

// ---------------- readout: q = relu([gout[batch], x_emb]) @ W_r + b_r ----------
__global__ void k_final(const float* __restrict__ Wr, const float* __restrict__ br,
                        float* __restrict__ out) {
    int gidx = blockIdx.x * blockDim.x + threadIdx.x;
    int n = gidx >> 5;
    int lane = threadIdx.x & 31;
    if (n >= NN) return;
    int b = g_batch[n];
    float acc = fmaxf(g_gout[b * DD + lane], 0.f)       * Wr[lane]
              + fmaxf(g_gout[b * DD + 32 + lane], 0.f)  * Wr[32 + lane]
              + g_xembB[n * DD + lane]                   * Wr[DD + lane]      // x_emb >= 0
              + g_xembB[n * DD + 32 + lane]              * Wr[DD + 32 + lane];
#pragma unroll
    for (int s = 16; s > 0; s >>= 1) acc += __shfl_down_sync(0xffffffffu, acc, s);
    if (lane == 0) out[n] = acc + br[0];
}

// ---------------- launch --------------------------------------------------------
extern "C" void kernel_launch(void* const* d_in, const int* in_sizes, int n_in,
                              void* d_out, int out_size) {
    const float* x      = (const float*)d_in[0];
    const void*  eidx   = d_in[1];
    const float* ea     = (const float*)d_in[2];
    const void*  batch  = d_in[3];
    const float* degree = (const float*)d_in[4];
    int wb = (n_in >= 20) ? 6 : 5;
    const float* W_en  = (const float*)d_in[wb + 0];
    const float* b_en  = (const float*)d_in[wb + 1];
    const float* W_ene = (const float*)d_in[wb + 2];
    const float* b_ene = (const float*)d_in[wb + 3];
    const float* W_agg = (const float*)d_in[wb + 4];
    const float* b_agg = (const float*)d_in[wb + 5];
    const float* Wm    = (const float*)d_in[wb + 6];
    const float* bm    = (const float*)d_in[wb + 7];
    const float* Wu    = (const float*)d_in[wb + 8];
    const float* bu    = (const float*)d_in[wb + 9];
    const float* W_g   = (const float*)d_in[wb + 10];
    const float* b_g   = (const float*)d_in[wb + 11];
    const float* W_r   = (const float*)d_in[wb + 12];
    const float* b_r   = (const float*)d_in[wb + 13];
    float* out = (float*)d_out;

    k_detect<<<1, 32>>>((const int*)eidx, 2 * NE, 0);
    k_detect<<<1, 32>>>((const int*)batch, NN, 1);
    k_zero<<<(GG * 16 + NN / 4 + 255) / 256, 256>>>();
    k_conv_edges<<<(NE + 255) / 256, 256>>>(eidx);
    k_conv_batch<<<(NN + 255) / 256, 256>>>(batch, degree);

    // CSR build
    k_scanA<<<NB_SCAN, 256>>>();
    k_scanB<<<1, 256>>>();
    k_scanC<<<NB_SCAN, 256>>>();
    k_scatter<<<(NE + 255) / 256, 256>>>(ea);

    k_nodeemb<<<(NN + 3) / 4, 256>>>(x, W_en, b_en);
    k_node2<<<(NN + 3) / 4, 256>>>(x, W_ene, b_ene, W_agg, b_agg);

    for (int l = 0; l < 3; l++) {
        k_layer<<<(NN + NT - 1) / NT, 256>>>(Wm + l * 2 * DD * DD, bm + l * DD,
                                             Wu + l * 2 * DD * DD, bu + l * DD, l & 1);
    }

    k_gscatter<<<(NN + 255) / 256, 256>>>();
    k_ggemm<<<(GG * DD + 255) / 256, 256>>>(W_g, b_g);
    k_final<<<(NN * 32 + 255) / 256, 256>>>(W_r, b_r, out);
}

// round 9
// speedup vs baseline: 2.2696x; 1.1424x over previous
#include <cuda_runtime.h>

#define NN 50000
#define NE 800000
#define DIN 7
#define DD 64
#define GG 64
#define NB_SCAN 196   // ceil(NN/256)
#define NT 32         // nodes per k_layer / k_node2 block
#define PAD 36        // padded row stride (144B: 16B aligned)

// ---------------- scratch (device globals; no allocation allowed) -------------
__device__ float g_xembA[NN * DD];
__device__ float g_xembB[NN * DD];
__device__ float g_xaggemb[NN * DD];
__device__ float g_degmax[GG];
__device__ float g_gagg[GG * DD];
__device__ float g_gcnt[GG];
__device__ float g_gout[GG * DD];
__device__ int   g_col[NE];
__device__ int   g_row[NE];
__device__ int2  g_cw[NE];          // sorted-by-row packed {col, w_bits}
__device__ int   g_rowptr[NN + 1];
__device__ int   g_cnt[NN];         // histogram
__device__ int   g_cnt2[NN];        // scatter cursors
__device__ int   g_bsum[NB_SCAN];
__device__ int   g_boff[NB_SCAN];
__device__ int   g_batch[NN];
__device__ int   g_flag[2];         // 1 => input is int64, 0 => int32

// ---------------- packed f32x2 helpers (sm_100+) -------------------------------
__device__ __forceinline__ unsigned long long pack2(float w) {
    unsigned long long r;
    asm("mov.b64 %0, {%1, %1};" : "=l"(r) : "f"(w));
    return r;
}
__device__ __forceinline__ void ffma2(unsigned long long& d,
                                      unsigned long long a, unsigned long long b) {
    asm("fma.rn.f32x2 %0, %1, %2, %0;" : "+l"(d) : "l"(a), "l"(b));
}
__device__ __forceinline__ void lds_pair(unsigned long long& a, unsigned long long& b,
                                         const float* p) {
    unsigned addr = (unsigned)__cvta_generic_to_shared(p);
    asm("ld.shared.v2.b64 {%0, %1}, [%2];" : "=l"(a), "=l"(b) : "r"(addr));
}
__device__ __forceinline__ float2 unpack2(unsigned long long v) {
    float2 f;
    asm("mov.b64 {%0, %1}, %2;" : "=f"(f.x), "=f"(f.y) : "l"(v));
    return f;
}

// ---------------- vector reduction helper (sm_90+) ----------------------------
__device__ __forceinline__ void red4(float* p, float4 v) {
    asm volatile("red.global.add.v4.f32 [%0], {%1,%2,%3,%4};"
                 :: "l"(p), "f"(v.x), "f"(v.y), "f"(v.z), "f"(v.w)
                 : "memory");
}

// ---------------- dtype detection ---------------------------------------------
__global__ void k_detect(const int* __restrict__ p, int n32, int slot) {
    int t = threadIdx.x;                 // 32 threads
    long long half = (long long)(n32 - 1) / 2;
    long long k = (half > 32) ? ((long long)t * (half - 1)) / 31 : (long long)t;
    long long idx = 2 * k + 1;
    int v = (idx < n32) ? p[idx] : 0;
    unsigned m = __ballot_sync(0xffffffffu, v == 0);
    if (t == 0) g_flag[slot] = (m == 0xffffffffu) ? 1 : 0;
}

// ---------------- zero (ints + pooling buffers) --------------------------------
__global__ void k_zero() {
    int i = blockIdx.x * blockDim.x + threadIdx.x;
    int4 zi = make_int4(0, 0, 0, 0);
    float4 zf = make_float4(0.f, 0.f, 0.f, 0.f);
    if (i < NN / 4) { ((int4*)g_cnt)[i] = zi; ((int4*)g_cnt2)[i] = zi; }
    if (i < GG * 16) ((float4*)g_gagg)[i] = zf;
    if (i < GG / 4) { ((float4*)g_degmax)[i] = zf; ((float4*)g_gcnt)[i] = zf; }
}

// edge conversion + row histogram
__global__ void k_conv_edges(const void* __restrict__ p) {
    int e = blockIdx.x * blockDim.x + threadIdx.x;
    if (e >= NE) return;
    int c, r;
    if (g_flag[0]) {
        const long long* q = (const long long*)p;
        c = (int)q[e]; r = (int)q[NE + e];
    } else {
        const int* q = (const int*)p;
        c = q[e]; r = q[NE + e];
    }
    g_col[e] = c;
    g_row[e] = r;
    atomicAdd(&g_cnt[r], 1);
}

// batch conversion + per-graph degree max + per-graph node count (fused)
__global__ void k_conv_batch(const void* __restrict__ p, const float* __restrict__ degree) {
    int n = blockIdx.x * blockDim.x + threadIdx.x;
    if (n >= NN) return;
    int b;
    if (g_flag[1]) b = (int)((const long long*)p)[n];
    else           b = ((const int*)p)[n];
    g_batch[n] = b;
    atomicMax((unsigned int*)&g_degmax[b], __float_as_uint(degree[n]));
    atomicAdd(&g_gcnt[b], 1.f);
}

// ---------------- 3-kernel exclusive scan of g_cnt -> g_rowptr -----------------
__global__ void k_scanA() {                         // 196 blocks x 256
    __shared__ int sh[256];
    int i = blockIdx.x * 256 + threadIdx.x;
    sh[threadIdx.x] = (i < NN) ? g_cnt[i] : 0;
    __syncthreads();
    for (int s = 128; s > 0; s >>= 1) {
        if (threadIdx.x < s) sh[threadIdx.x] += sh[threadIdx.x + s];
        __syncthreads();
    }
    if (threadIdx.x == 0) g_bsum[blockIdx.x] = sh[0];
}

__global__ void k_scanB() {                         // 1 block x 256
    __shared__ int sh[256];
    int t = threadIdx.x;
    int v = (t < NB_SCAN) ? g_bsum[t] : 0;
    sh[t] = v;
    __syncthreads();
    for (int s = 1; s < 256; s <<= 1) {
        int add = (t >= s) ? sh[t - s] : 0;
        __syncthreads();
        sh[t] += add;
        __syncthreads();
    }
    if (t < NB_SCAN) g_boff[t] = sh[t] - v;         // exclusive
    if (t == 0) g_rowptr[NN] = NE;
}

__global__ void k_scanC() {                         // 196 blocks x 256
    __shared__ int sh[256];
    int t = threadIdx.x;
    int i = blockIdx.x * 256 + t;
    int v = (i < NN) ? g_cnt[i] : 0;
    sh[t] = v;
    __syncthreads();
    for (int s = 1; s < 256; s <<= 1) {
        int add = (t >= s) ? sh[t - s] : 0;
        __syncthreads();
        sh[t] += add;
        __syncthreads();
    }
    if (i < NN) g_rowptr[i] = g_boff[blockIdx.x] + sh[t] - v;
}

// scatter edges into CSR order, packing {col, w}
__global__ void k_scatter(const float* __restrict__ ea) {
    int e = blockIdx.x * blockDim.x + threadIdx.x;
    if (e >= NE) return;
    int r = g_row[e];
    int pos = g_rowptr[r] + atomicAdd(&g_cnt2[r], 1);
    g_cw[pos] = make_int2(g_col[e], __float_as_int(ea[e]));
}

// ---------------- node embedding: x_emb = relu(x @ W_en + b_en) ---------------
__global__ void k_nodeemb(const float* __restrict__ x,
                          const float* __restrict__ W,
                          const float* __restrict__ b) {
    __shared__ float sx[4][DIN];
    int gl = threadIdx.x >> 6, o = threadIdx.x & 63;
    int n = blockIdx.x * 4 + gl;
    if (o < DIN && n < NN) sx[gl][o] = x[n * DIN + o];
    __syncthreads();
    if (n >= NN) return;
    float acc = b[o];
#pragma unroll
    for (int i = 0; i < DIN; i++) acc = fmaf(sx[gl][i], W[i * DD + o], acc);
    g_xembA[n * DD + o] = fmaxf(acc, 0.f);
}

// ---------------- fused stage-2: 32 nodes/block -------------------------------
// gather: thread = (node ln=t>>3, feature f=t&7), walks full edge list.
// ene GEMM (8->63) scalar; Wagg GEMM (64->64) register-blocked + FFMA2.
__global__ void __launch_bounds__(256) k_node2(
        const float* __restrict__ x,
        const float* __restrict__ Wene, const float* __restrict__ bene,
        const float* __restrict__ Wagg, const float* __restrict__ bagg) {
    __shared__ __align__(16) float act[DD][PAD];
    __shared__ float ne[NT][9];
    __shared__ float rcs[NT];
    int t = threadIdx.x;
    int n0 = blockIdx.x * NT;

    // ---- gather ----
    {
        int ln = t >> 3, f = t & 7;
        int n = n0 + ln;
        float acc = 0.f;
        int deg = 0;
        if (n < NN) {
            int p0 = g_rowptr[n];
            deg = g_rowptr[n + 1] - p0;
            for (int k = 0; k < deg; k++) {
                int2 cw = g_cw[p0 + k];
                acc += (f < 7) ? x[cw.x * DIN + f] : __int_as_float(cw.y);
            }
        }
        ne[ln][f] = acc;
        if (f == 0) rcs[ln] = 1.f / fmaxf((float)deg, 1.f);
    }
    __syncthreads();

    // ---- ene GEMM + degree slot -> act[o][node] ----
    {
        int gl = t >> 6, o = t & 63;
        float wv[8], b0 = 0.f;
        if (o < 63) {
            b0 = bene[o];
#pragma unroll
            for (int j = 0; j < 8; j++) wv[j] = Wene[j * 63 + o];
        }
#pragma unroll
        for (int i = 0; i < 8; i++) {
            int node = gl * 8 + i;
            int n = n0 + node;
            float v;
            if (o < 63) {
                float rc = rcs[node];
                float a = b0;
#pragma unroll
                for (int j = 0; j < 8; j++) a = fmaf(ne[node][j] * rc, wv[j], a);
                v = fmaxf(a, 0.f);
            } else {
                v = (n < NN) ? g_degmax[g_batch[n]] : 0.f;
            }
            act[o][node] = v;
        }
    }
    __syncthreads();

    // ---- Wagg GEMM (FFMA2): x_agg_emb = relu(act @ Wagg + bagg) ----
    {
        int gl = t >> 6, o = t & 63;
        unsigned long long m01, m23, m45, m67;
        m01 = m23 = m45 = m67 = pack2(bagg[o]);
#pragma unroll 4
        for (int j = 0; j < DD; j++) {
            unsigned long long ww = pack2(Wagg[j * DD + o]);
            unsigned long long a0, a1, a2, a3;
            lds_pair(a0, a1, &act[j][gl * 8]);
            lds_pair(a2, a3, &act[j][gl * 8 + 4]);
            ffma2(m01, ww, a0); ffma2(m23, ww, a1);
            ffma2(m45, ww, a2); ffma2(m67, ww, a3);
        }
        float2 r0 = unpack2(m01), r1 = unpack2(m23);
        float2 r2 = unpack2(m45), r3 = unpack2(m67);
        float res[8] = {r0.x, r0.y, r1.x, r1.y, r2.x, r2.y, r3.x, r3.y};
#pragma unroll
        for (int i = 0; i < 8; i++) {
            int n = n0 + gl * 8 + i;
            if (n < NN) g_xaggemb[n * DD + o] = fmaxf(res[i], 0.f);
        }
    }
}

// ---------------- fused per-layer: float2 gather + FFMA2 GEMMs ----------------
// Gather: warp-per-node (lane o2 = feature pair), 4 reps x 8 nodes.
// GEMM: thread (o, gl) computes column o for 8 nodes via 4 f32x2 accumulators.
__global__ void __launch_bounds__(256) k_layer(
        const float* __restrict__ Wm, const float* __restrict__ bm,
        const float* __restrict__ Wu, const float* __restrict__ bu,
        int flip) {
    const float* __restrict__ src = flip ? g_xembB : g_xembA;
    float*       __restrict__ dst = flip ? g_xembA : g_xembB;
    __shared__ __align__(16) float act1[2 * DD][PAD];   // [xagg*rc ; xaggemb]
    __shared__ __align__(16) float act2[2 * DD][PAD];   // [x_emb ; m]
    int t = threadIdx.x;
    int n0 = blockIdx.x * NT;

    // ---- gather phase ----
    {
        int o2 = t & 31;          // feature pair: features 2*o2, 2*o2+1
        int w8 = t >> 5;          // node slot 0..7
#pragma unroll 1
        for (int rep = 0; rep < 4; rep++) {
            int ln = rep * 8 + w8;
            int n = n0 + ln;
            unsigned long long acc = 0ULL, xe = 0ULL, xae = 0ULL;
            int deg = 0;
            if (n < NN) {
                int p0 = g_rowptr[n];
                deg = g_rowptr[n + 1] - p0;
                int k = 0;
                for (; k + 4 <= deg; k += 4) {
                    int2 c0 = g_cw[p0 + k],     c1 = g_cw[p0 + k + 1];
                    int2 c2 = g_cw[p0 + k + 2], c3 = g_cw[p0 + k + 3];
                    unsigned long long v0 = *(const unsigned long long*)&src[c0.x * DD + 2 * o2];
                    unsigned long long v1 = *(const unsigned long long*)&src[c1.x * DD + 2 * o2];
                    unsigned long long v2 = *(const unsigned long long*)&src[c2.x * DD + 2 * o2];
                    unsigned long long v3 = *(const unsigned long long*)&src[c3.x * DD + 2 * o2];
                    ffma2(acc, pack2(__int_as_float(c0.y)), v0);
                    ffma2(acc, pack2(__int_as_float(c1.y)), v1);
                    ffma2(acc, pack2(__int_as_float(c2.y)), v2);
                    ffma2(acc, pack2(__int_as_float(c3.y)), v3);
                }
                for (; k < deg; k++) {
                    int2 cw = g_cw[p0 + k];
                    unsigned long long v = *(const unsigned long long*)&src[cw.x * DD + 2 * o2];
                    ffma2(acc, pack2(__int_as_float(cw.y)), v);
                }
                xe  = *(const unsigned long long*)&src[n * DD + 2 * o2];
                xae = *(const unsigned long long*)&g_xaggemb[n * DD + 2 * o2];
            }
            float rc = 1.f / fmaxf((float)deg, 1.f);
            float2 a = unpack2(acc), x2 = unpack2(xe), xa2 = unpack2(xae);
            act1[2 * o2][ln]          = a.x * rc;
            act1[2 * o2 + 1][ln]      = a.y * rc;
            act1[DD + 2 * o2][ln]     = xa2.x;
            act1[DD + 2 * o2 + 1][ln] = xa2.y;
            act2[2 * o2][ln]          = x2.x;
            act2[2 * o2 + 1][ln]      = x2.y;
        }
    }
    __syncthreads();

    int gl = t >> 6, o = t & 63;

    // ---- GEMM1: m = relu([xagg, xaggemb] @ Wm + bm) ----
    {
        unsigned long long m01, m23, m45, m67;
        m01 = m23 = m45 = m67 = pack2(bm[o]);
#pragma unroll 4
        for (int j = 0; j < 2 * DD; j++) {
            unsigned long long ww = pack2(Wm[j * DD + o]);
            unsigned long long a0, a1, a2, a3;
            lds_pair(a0, a1, &act1[j][gl * 8]);
            lds_pair(a2, a3, &act1[j][gl * 8 + 4]);
            ffma2(m01, ww, a0); ffma2(m23, ww, a1);
            ffma2(m45, ww, a2); ffma2(m67, ww, a3);
        }
        float2 r0 = unpack2(m01), r1 = unpack2(m23);
        float2 r2 = unpack2(m45), r3 = unpack2(m67);
        float* row = &act2[DD + o][gl * 8];
        row[0] = fmaxf(r0.x, 0.f); row[1] = fmaxf(r0.y, 0.f);
        row[2] = fmaxf(r1.x, 0.f); row[3] = fmaxf(r1.y, 0.f);
        row[4] = fmaxf(r2.x, 0.f); row[5] = fmaxf(r2.y, 0.f);
        row[6] = fmaxf(r3.x, 0.f); row[7] = fmaxf(r3.y, 0.f);
    }
    __syncthreads();

    // ---- GEMM2: x_emb' = relu([x_emb, m] @ Wu + bu) ----
    {
        unsigned long long m01, m23, m45, m67;
        m01 = m23 = m45 = m67 = pack2(bu[o]);
#pragma unroll 4
        for (int j = 0; j < 2 * DD; j++) {
            unsigned long long ww = pack2(Wu[j * DD + o]);
            unsigned long long a0, a1, a2, a3;
            lds_pair(a0, a1, &act2[j][gl * 8]);
            lds_pair(a2, a3, &act2[j][gl * 8 + 4]);
            ffma2(m01, ww, a0); ffma2(m23, ww, a1);
            ffma2(m45, ww, a2); ffma2(m67, ww, a3);
        }
        float2 r0 = unpack2(m01), r1 = unpack2(m23);
        float2 r2 = unpack2(m45), r3 = unpack2(m67);
        float res[8] = {r0.x, r0.y, r1.x, r1.y, r2.x, r2.y, r3.x, r3.y};
#pragma unroll
        for (int i = 0; i < 8; i++) {
            int n = n0 + gl * 8 + i;
            if (n < NN) dst[n * DD + o] = fmaxf(res[i], 0.f);
        }
    }
}

// ---------------- graph pooling: sorted-batch local accumulation --------------
__global__ void k_gscatter() {
    int idx = blockIdx.x * blockDim.x + threadIdx.x;   // 50000 threads
    int c  = idx & 15;
    int n0 = (idx >> 4) * 16;
    if (n0 >= NN) return;
    float4 acc = make_float4(0.f, 0.f, 0.f, 0.f);
    int curb = g_batch[n0];
#pragma unroll
    for (int k = 0; k < 16; k++) {
        int n = n0 + k;
        int b = g_batch[n];
        if (b != curb) {
            red4(g_gagg + curb * DD + c * 4, acc);
            acc = make_float4(0.f, 0.f, 0.f, 0.f);
            curb = b;
        }
        float4 v = ((const float4*)g_xembB)[n * 16 + c];
        acc.x += v.x; acc.y += v.y; acc.z += v.z; acc.w += v.w;
    }
    red4(g_gagg + curb * DD + c * 4, acc);
}

__global__ void k_ggemm(const float* __restrict__ Wg, const float* __restrict__ bg) {
    int idx = blockIdx.x * blockDim.x + threadIdx.x;
    if (idx >= GG * DD) return;
    int g = idx >> 6, o = idx & 63;
    float rc = 1.f / fmaxf(g_gcnt[g], 1.f);
    float acc = bg[o];
#pragma unroll 16
    for (int k = 0; k < DD; k++)
        acc = fmaf(g_gagg[g * DD + k] * rc, Wg[k * DD + o], acc);
    g_gout[idx] = acc;   // no relu (reference applies relu to the concat input)
}

// ---------------- readout: q = relu([gout[batch], x_emb]) @ W_r + b_r ----------
__global__ void k_final(const float* __restrict__ Wr, const float* __restrict__ br,
                        float* __restrict__ out) {
    int gidx = blockIdx.x * blockDim.x + threadIdx.x;
    int n = gidx >> 5;
    int lane = threadIdx.x & 31;
    if (n >= NN) return;
    int b = g_batch[n];
    float acc = fmaxf(g_gout[b * DD + lane], 0.f)       * Wr[lane]
              + fmaxf(g_gout[b * DD + 32 + lane], 0.f)  * Wr[32 + lane]
              + g_xembB[n * DD + lane]                   * Wr[DD + lane]      // x_emb >= 0
              + g_xembB[n * DD + 32 + lane]              * Wr[DD + 32 + lane];
#pragma unroll
    for (int s = 16; s > 0; s >>= 1) acc += __shfl_down_sync(0xffffffffu, acc, s);
    if (lane == 0) out[n] = acc + br[0];
}

// ---------------- launch --------------------------------------------------------
extern "C" void kernel_launch(void* const* d_in, const int* in_sizes, int n_in,
                              void* d_out, int out_size) {
    const float* x      = (const float*)d_in[0];
    const void*  eidx   = d_in[1];
    const float* ea     = (const float*)d_in[2];
    const void*  batch  = d_in[3];
    const float* degree = (const float*)d_in[4];
    int wb = (n_in >= 20) ? 6 : 5;
    const float* W_en  = (const float*)d_in[wb + 0];
    const float* b_en  = (const float*)d_in[wb + 1];
    const float* W_ene = (const float*)d_in[wb + 2];
    const float* b_ene = (const float*)d_in[wb + 3];
    const float* W_agg = (const float*)d_in[wb + 4];
    const float* b_agg = (const float*)d_in[wb + 5];
    const float* Wm    = (const float*)d_in[wb + 6];
    const float* bm    = (const float*)d_in[wb + 7];
    const float* Wu    = (const float*)d_in[wb + 8];
    const float* bu    = (const float*)d_in[wb + 9];
    const float* W_g   = (const float*)d_in[wb + 10];
    const float* b_g   = (const float*)d_in[wb + 11];
    const float* W_r   = (const float*)d_in[wb + 12];
    const float* b_r   = (const float*)d_in[wb + 13];
    float* out = (float*)d_out;

    k_detect<<<1, 32>>>((const int*)eidx, 2 * NE, 0);
    k_detect<<<1, 32>>>((const int*)batch, NN, 1);
    k_zero<<<(GG * 16 + NN / 4 + 255) / 256, 256>>>();
    k_conv_edges<<<(NE + 255) / 256, 256>>>(eidx);
    k_conv_batch<<<(NN + 255) / 256, 256>>>(batch, degree);

    // CSR build
    k_scanA<<<NB_SCAN, 256>>>();
    k_scanB<<<1, 256>>>();
    k_scanC<<<NB_SCAN, 256>>>();
    k_scatter<<<(NE + 255) / 256, 256>>>(ea);

    k_nodeemb<<<(NN + 3) / 4, 256>>>(x, W_en, b_en);
    k_node2<<<(NN + NT - 1) / NT, 256>>>(x, W_ene, b_ene, W_agg, b_agg);

    for (int l = 0; l < 3; l++) {
        k_layer<<<(NN + NT - 1) / NT, 256>>>(Wm + l * 2 * DD * DD, bm + l * DD,
                                             Wu + l * 2 * DD * DD, bu + l * DD, l & 1);
    }

    k_gscatter<<<(NN + 255) / 256, 256>>>();
    k_ggemm<<<(GG * DD + 255) / 256, 256>>>(W_g, b_g);
    k_final<<<(NN * 32 + 255) / 256, 256>>>(W_r, b_r, out);
}